// round 12
// baseline (speedup 1.0000x reference)
#include <cuda_runtime.h>
#include <cuda_bf16.h>

// NormalsRenderer: B=512, N=512.
// out[b] = normalize( sum_i acc_i * n_i ),  acc_i = sum_{j!=i} exp(-acos(clip(<n_i,n_j>)))
// Identities (uniform positive scales cancel under the final normalize):
//   - division by max(new_weights) dropped; exp(-acos d) = const * exp(asin d)
//   - u = sat(1-|d|);  asin(|d|)*log2e = LHPI + sqrt(u)*Q(u)  (cubic Q)
//   - w = exp2( copysign( LHPI + sqrt(u)*Q(u), d ) )
// 512 rows = 16 groups of 32. The 136 unordered group-tiles are covered exactly once
// by 40 chunks (i-run of <=4 groups x 1 j-group, diag group always last in its run),
// distributed over 16 warps/batch (8 warps x 2 CTAs): 8 warps get 8 tiles, 8 get 9.
// ALL-SCALAR eval (no f32x2): the packed path's pack/unpack MOV marshaling cost more
// issue slots than the packed FFMAs saved (measured R9..R11).
// Lane l holds one i-row per group in regs; j-row rotates via shfl with a traveling
// column accumulator (1 shfl each + 3 j shfls per step, amortized over <=4 evals).
// Diag: colacc excludes the last group via fmaf(last, cmask, rest); the s=0 self term
// stays in rowacc and one bitwise-identical eval1(self) is subtracted at flush.
// 2 CTAs/batch (grid 1024, 256 thr, <=36 regs -> 7 CTAs/SM single wave); per-warp
// smem row accumulators, CTA reduce, cross-CTA atomic merge (2nd finisher writes).

#define NPTS 512
#define TPB  256

typedef unsigned int uint;

// -log2(e) * p_AS(1-u) re-expanded in u, and log2(e)*pi/2
#define Q0f (-2.0401824f)
#define Q1f (-0.17280645f)
#define Q2f (-0.026074023f)
#define Q3f (-0.027020667f)
#define LHPIf (2.2661800709f)

__device__ float g_stage[1024][3];
__device__ int   g_cnt[512];

// chunk tables: warp W (0..15) runs up to 3 chunks (gj, gib, ng); ng=0 sentinel.
// Exact cover of all 136 (i<=j) group-tiles; diag iff gib+ng-1 == gj (always last).
__constant__ signed char c_gj[16][3] = {
    {3,15,-1},{4,15,-1},{5,15,-1},{6,14,-1},{7,14,-1},{8,13,-1},{9,13,-1},{10,12,-1},
    {11,12,4},{12,11,8},{13,11,12},{14,10,0},{15,2,1},{7,6,5},{8,10,9},{9,14,13}};
__constant__ signed char c_gib[16][3] = {
    {0,0,0},{1,4,0},{2,8,0},{3,3,0},{4,7,0},{5,2,0},{6,6,0},{7,1,0},
    {8,5,0},{9,0,0},{10,4,0},{11,3,0},{12,0,0},{0,0,0},{1,0,0},{2,0,0}};
__constant__ signed char c_ng[16][3] = {
    {4,4,0},{4,4,0},{4,4,0},{4,4,0},{4,4,0},{4,4,0},{4,4,0},{4,4,0},
    {4,4,1},{4,4,1},{4,4,1},{4,4,1},{4,3,2},{4,3,2},{4,3,2},{4,3,2}};

__device__ __forceinline__ float sqrta(float x) {
    float r; asm("sqrt.approx.f32 %0, %1;" : "=f"(r) : "f"(x)); return r;
}
__device__ __forceinline__ float ex2a(float x) {
    float r; asm("ex2.approx.f32 %0, %1;" : "=f"(r) : "f"(x)); return r;
}

__device__ __forceinline__ float eval1(float xi, float yi, float zi,
                                       float jx, float jy, float jz)
{
    float d = fmaf(zi, jz, fmaf(yi, jy, xi * jx));
    float u = __saturatef(1.0f - fabsf(d));
    float s = sqrta(u);
    float p = fmaf(u, Q3f, Q2f);
    p = fmaf(u, p, Q1f);
    p = fmaf(u, p, Q0f);
    float g = fmaf(s, p, LHPIf);
    uint  e = __float_as_uint(g) | (__float_as_uint(d) & 0x80000000u);
    return ex2a(__uint_as_float(e));
}

template<int NG>
__device__ __forceinline__ void process_chunk(const float4* __restrict__ sn4,
                                              float* __restrict__ raw,
                                              int gj, int gib, bool diag,
                                              int lane, int srcp)
{
    float xi[NG], yi[NG], zi[NG], ra[NG];
    #pragma unroll
    for (int g = 0; g < NG; ++g) {
        float4 a = sn4[(gib + g) * 32 + lane];
        xi[g] = a.x; yi[g] = a.y; zi[g] = a.z; ra[g] = 0.0f;
    }
    float4 nj = sn4[gj * 32 + lane];
    float jx = nj.x, jy = nj.y, jz = nj.z;
    float colacc = 0.0f;
    const float cmask = diag ? 0.0f : 1.0f;   // last group excluded from colacc if diag

    #pragma unroll 4
    for (int s = 0; s < 32; ++s) {
        float rest = 0.0f, last = 0.0f;
        #pragma unroll
        for (int g = 0; g < NG; ++g) {
            float w = eval1(xi[g], yi[g], zi[g], jx, jy, jz);
            ra[g] += w;
            if (g < NG - 1) rest += w; else last = w;
        }
        colacc = fmaf(last, cmask, colacc + rest);
        colacc = __shfl_sync(0xffffffffu, colacc, srcp);
        jx = __shfl_sync(0xffffffffu, jx, srcp);
        jy = __shfl_sync(0xffffffffu, jy, srcp);
        jz = __shfl_sync(0xffffffffu, jz, srcp);
    }

    // Diag correction: s=0 computed the self pair through the SAME scalar code path
    // -> bitwise-identical value -> exact cancel on subtraction.
    float selfw = 0.0f;
    if (diag) {
        float4 n = sn4[gj * 32 + lane];
        selfw = eval1(n.x, n.y, n.z, n.x, n.y, n.z);
    }

    #pragma unroll
    for (int g = 0; g < NG; ++g) {
        float v = ra[g];
        if (g == NG - 1) v -= selfw;
        raw[(gib + g) * 32 + lane] += v;
    }
    raw[gj * 32 + lane] += colacc;   // aligned to column `lane` after 32 rotations
}

__global__ __launch_bounds__(TPB, 7)
void normals_scalar_kernel(const float* __restrict__ normals,
                           float* __restrict__ out)
{
    __shared__ float4 sn4[NPTS];          // 8 KB
    __shared__ float  rowaccW[8][NPTS];   // 16 KB per-warp row accumulators
    __shared__ float  sred[3][8];

    const int b    = blockIdx.x >> 1;
    const int half = blockIdx.x & 1;
    const int t    = threadIdx.x;
    const int lane = t & 31;
    const int wl   = t >> 5;              // 0..7
    const int srcp = (lane + 1) & 31;

    const float* base = normals + (size_t)b * NPTS * 3;
    #pragma unroll
    for (int r = t; r < NPTS; r += TPB)
        sn4[r] = make_float4(base[r * 3 + 0], base[r * 3 + 1], base[r * 3 + 2], 0.0f);
    #pragma unroll
    for (int idx = t; idx < 8 * NPTS; idx += TPB)
        ((float*)rowaccW)[idx] = 0.0f;
    __syncthreads();

    const int W = half * 8 + wl;          // global warp id 0..15
    float* raw = rowaccW[wl];

    #pragma unroll 1
    for (int c = 0; c < 3; ++c) {
        const int ng = c_ng[W][c];
        if (ng == 0) break;
        const int gj  = c_gj[W][c];
        const int gib = c_gib[W][c];
        const bool dg = (gib + ng - 1 == gj);
        switch (ng) {
            case 4: process_chunk<4>(sn4, raw, gj, gib, dg, lane, srcp); break;
            case 3: process_chunk<3>(sn4, raw, gj, gib, dg, lane, srcp); break;
            case 2: process_chunk<2>(sn4, raw, gj, gib, dg, lane, srcp); break;
            default: process_chunk<1>(sn4, raw, gj, gib, dg, lane, srcp); break;
        }
    }
    __syncthreads();

    // weighted sum over rows handled by this thread (2 rows each)
    float vx = 0.0f, vy = 0.0f, vz = 0.0f;
    #pragma unroll
    for (int r = t; r < NPTS; r += TPB) {
        float wsum = ((rowaccW[0][r] + rowaccW[1][r]) + (rowaccW[2][r] + rowaccW[3][r]))
                   + ((rowaccW[4][r] + rowaccW[5][r]) + (rowaccW[6][r] + rowaccW[7][r]));
        float4 n = sn4[r];
        vx = fmaf(wsum, n.x, vx);
        vy = fmaf(wsum, n.y, vy);
        vz = fmaf(wsum, n.z, vz);
    }

    #pragma unroll
    for (int s = 16; s >= 1; s >>= 1) {
        vx += __shfl_down_sync(0xffffffffu, vx, s);
        vy += __shfl_down_sync(0xffffffffu, vy, s);
        vz += __shfl_down_sync(0xffffffffu, vz, s);
    }
    if (lane == 0) { sred[0][wl] = vx; sred[1][wl] = vy; sred[2][wl] = vz; }
    __syncthreads();

    if (t == 0) {
        float rx = 0.0f, ry = 0.0f, rz = 0.0f;
        #pragma unroll
        for (int wI = 0; wI < 8; ++wI) {
            rx += sred[0][wI]; ry += sred[1][wI]; rz += sred[2][wI];
        }
        g_stage[blockIdx.x][0] = rx;
        g_stage[blockIdx.x][1] = ry;
        g_stage[blockIdx.x][2] = rz;
        __threadfence();
        int old = atomicAdd(&g_cnt[b], 1);
        if (old == 1) {
            __threadfence();
            const int other = blockIdx.x ^ 1;
            rx += g_stage[other][0];
            ry += g_stage[other][1];
            rz += g_stage[other][2];
            float ss  = fmaf(rx, rx, fmaf(ry, ry, rz * rz));
            float inv = rsqrtf(fmaxf(ss, 1e-20f));
            out[b * 3 + 0] = rx * inv;
            out[b * 3 + 1] = ry * inv;
            out[b * 3 + 2] = rz * inv;
            g_cnt[b] = 0;   // deterministic state for graph replay
        }
    }
}

extern "C" void kernel_launch(void* const* d_in, const int* in_sizes, int n_in,
                              void* d_out, int out_size)
{
    const float* normals = (const float*)d_in[0];  // [512, 512, 3] f32
    // d_in[1] = weights: unused by the reference math.
    float* out = (float*)d_out;                    // [512, 3] f32

    normals_scalar_kernel<<<1024, TPB>>>(normals, out);
}

// round 13
// speedup vs baseline: 1.1835x; 1.1835x over previous
#include <cuda_runtime.h>
#include <cuda_bf16.h>

// NormalsRenderer: B=512, N=512.
// out[b] = normalize( sum_i acc_i * n_i ),  acc_i = sum_{j!=i} exp(-acos(clip(<n_i,n_j>)))
// Identities (uniform positive scales cancel under the final normalize):
//   - division by max(new_weights) dropped; exp(-acos d) = const * exp(asin d)
//   - u = sat(1-|d|);  asin(|d|)*log2e = LHPI + sqrt(u)*Q(u)  (cubic Q)
//   - w = exp2( copysign( LHPI + sqrt(u)*Q(u), d ) )
// 512 rows = 16 groups of 32; 136 unordered group-tiles covered once by 40 chunks
// (<=4 i-groups x 1 j-group), 5 chunks per warp, 8 warps/batch (R9's proven table).
// BROADCAST-J inner loop: normals live in smem as pre-duplicated packed pairs
// sdx[k]=(x_k,x_k); at step s all lanes read j-row gj*32+s with 3 broadcast LDS.64
// (crossbar-free, already in f32x2 form -> kills R9's 3 j-shfls + 6 dup-MOVs/step).
// Column sums: 5-shfl butterfly per step; lane s keeps the total (predicated add),
// so after 32 steps lane l holds the col sum for j-row gj*32+l.
// Diag chunk: diag group is LAST; excluded from col via fmaf(last,cmask,rest); the
// self term stays in rowacc and a bitwise-identical eval is subtracted at flush.
// 2 CTAs/batch (grid 1024, 128 thr); per-warp smem row accumulators, CTA reduce,
// cross-CTA merge via atomic counter (second finisher normalizes + writes).

#define NPTS 512
#define TPB  128

typedef unsigned long long ull;
typedef unsigned int uint;

// -log2(e) * p_AS(1-u) re-expanded in u, and log2(e)*pi/2
#define Q0f (-2.0401824f)
#define Q1f (-0.17280645f)
#define Q2f (-0.026074023f)
#define Q3f (-0.027020667f)
#define LHPIf (2.2661800709f)

__device__ float g_stage[1024][3];
__device__ int   g_cnt[512];

// R9's proven chunk tables: warp W (0..7) runs 5 chunks (gj, gib, ng).
// Exact cover of all 136 (i<=j) group-tiles; diag iff gib+ng-1 == gj (always last).
__constant__ signed char c_gj[8][5] = {
    {3,4,5,6,0}, {7,7,8,8,4}, {9,9,10,10,8}, {11,11,11,12,12},
    {12,12,13,2,1}, {13,13,14,6,5}, {14,14,15,10,9}, {15,15,15,14,13}};
__constant__ signed char c_gib[8][5] = {
    {0,0,0,0,0}, {0,4,0,4,4}, {0,4,0,4,8}, {0,4,8,0,12},
    {4,8,0,0,0}, {4,8,0,4,4}, {4,8,0,8,8}, {4,8,12,12,12}};
__constant__ signed char c_ng[8][5] = {
    {4,4,4,4,1}, {4,4,4,4,1}, {4,4,4,4,1}, {4,4,4,4,1},
    {4,4,4,3,2}, {4,4,4,3,2}, {4,4,4,3,2}, {4,4,4,3,2}};

__device__ __forceinline__ ull pack2(float lo, float hi) {
    ull r; asm("mov.b64 %0, {%1, %2};" : "=l"(r) : "f"(lo), "f"(hi)); return r;
}
__device__ __forceinline__ void unpack2(ull v, float& lo, float& hi) {
    asm("mov.b64 {%0, %1}, %2;" : "=f"(lo), "=f"(hi) : "l"(v));
}
__device__ __forceinline__ ull fma2(ull a, ull b, ull c) {
    ull d; asm("fma.rn.f32x2 %0, %1, %2, %3;" : "=l"(d) : "l"(a), "l"(b), "l"(c)); return d;
}
__device__ __forceinline__ ull mul2(ull a, ull b) {
    ull d; asm("mul.rn.f32x2 %0, %1, %2;" : "=l"(d) : "l"(a), "l"(b)); return d;
}
__device__ __forceinline__ ull add2(ull a, ull b) {
    ull d; asm("add.rn.f32x2 %0, %1, %2;" : "=l"(d) : "l"(a), "l"(b)); return d;
}
__device__ __forceinline__ float sqrta(float x) {
    float r; asm("sqrt.approx.f32 %0, %1;" : "=f"(r) : "f"(x)); return r;
}
__device__ __forceinline__ float ex2a(float x) {
    float r; asm("ex2.approx.f32 %0, %1;" : "=f"(r) : "f"(x)); return r;
}

__device__ __forceinline__ ull eval2(ull xi2, ull yi2, ull zi2,
                                     ull jx2, ull jy2, ull jz2)
{
    const ull q3v = pack2(Q3f, Q3f), q2v = pack2(Q2f, Q2f);
    const ull q1v = pack2(Q1f, Q1f), q0v = pack2(Q0f, Q0f);
    const ull lh2 = pack2(LHPIf, LHPIf);
    ull d2 = fma2(zi2, jz2, fma2(yi2, jy2, mul2(xi2, jx2)));
    float da, db; unpack2(d2, da, db);
    float ua = __saturatef(1.0f - fabsf(da));
    float ub = __saturatef(1.0f - fabsf(db));
    float sa = sqrta(ua), sb = sqrta(ub);
    ull u2 = pack2(ua, ub);
    ull p2 = fma2(u2, q3v, q2v);
    p2 = fma2(u2, p2, q1v);
    p2 = fma2(u2, p2, q0v);
    ull g2 = fma2(pack2(sa, sb), p2, lh2);
    float ga, gb; unpack2(g2, ga, gb);
    uint ea = __float_as_uint(ga) | (__float_as_uint(da) & 0x80000000u);
    uint eb = __float_as_uint(gb) | (__float_as_uint(db) & 0x80000000u);
    return pack2(ex2a(__uint_as_float(ea)), ex2a(__uint_as_float(eb)));
}

__device__ __forceinline__ float eval1(float xi, float yi, float zi,
                                       float jx, float jy, float jz)
{
    float d = fmaf(zi, jz, fmaf(yi, jy, xi * jx));
    float u = __saturatef(1.0f - fabsf(d));
    float s = sqrta(u);
    float p = fmaf(u, Q3f, Q2f);
    p = fmaf(u, p, Q1f);
    p = fmaf(u, p, Q0f);
    float g = fmaf(s, p, LHPIf);
    uint  e = __float_as_uint(g) | (__float_as_uint(d) & 0x80000000u);
    return ex2a(__uint_as_float(e));
}

// NP packed group-pairs + optional scalar tail. NG = 2*NP + HS. Diag group = last.
template<int NP, bool HS>
__device__ __forceinline__ void process_chunk(const ull* __restrict__ sdx,
                                              const ull* __restrict__ sdy,
                                              const ull* __restrict__ sdz,
                                              float* __restrict__ raw,
                                              int gj, int gib, bool diag, int lane)
{
    constexpr int NPA = (NP > 0) ? NP : 1;
    ull xi[NPA], yi[NPA], zi[NPA], ra[NPA];
    #pragma unroll
    for (int p = 0; p < NP; ++p) {
        const int rA = (gib + 2 * p) * 32 + lane;
        const int rB = (gib + 2 * p + 1) * 32 + lane;
        float ax, ay, az, t_, bx, by, bz;
        unpack2(sdx[rA], ax, t_); unpack2(sdx[rB], bx, t_);
        unpack2(sdy[rA], ay, t_); unpack2(sdy[rB], by, t_);
        unpack2(sdz[rA], az, t_); unpack2(sdz[rB], bz, t_);
        xi[p] = pack2(ax, bx); yi[p] = pack2(ay, by); zi[p] = pack2(az, bz);
        ra[p] = pack2(0.0f, 0.0f);
    }
    float xs = 0.0f, ys = 0.0f, zs = 0.0f, ras = 0.0f;
    if (HS) {
        const int r = (gib + 2 * NP) * 32 + lane;
        float t_;
        unpack2(sdx[r], xs, t_); unpack2(sdy[r], ys, t_); unpack2(sdz[r], zs, t_);
    }

    const int jbase = gj * 32;
    float colreg = 0.0f;
    const float cmask = diag ? 0.0f : 1.0f;   // last group excluded from col if diag

    #pragma unroll 4
    for (int s = 0; s < 32; ++s) {
        const ull jx2 = sdx[jbase + s];   // broadcast LDS.64, already (j,j) packed
        const ull jy2 = sdy[jbase + s];
        const ull jz2 = sdz[jbase + s];
        float rest = 0.0f, last;
        if (NP >= 1) {
            ull w0 = eval2(xi[0], yi[0], zi[0], jx2, jy2, jz2);
            ra[0] = add2(ra[0], w0);
            float a0, b0; unpack2(w0, a0, b0);
            if (NP == 1 && !HS) { rest = a0; last = b0; }
            else                  rest = a0 + b0;
        }
        if (NP == 2) {
            ull w1 = eval2(xi[1], yi[1], zi[1], jx2, jy2, jz2);
            ra[1] = add2(ra[1], w1);
            float a1, b1; unpack2(w1, a1, b1);
            if (!HS) { rest += a1; last = b1; }
            else       rest += a1 + b1;
        }
        if (HS) {
            float jxs, jys, jzs, t_;
            unpack2(jx2, jxs, t_); unpack2(jy2, jys, t_); unpack2(jz2, jzs, t_);
            float ws = eval1(xs, ys, zs, jxs, jys, jzs);
            ras += ws;
            last = ws;
        }
        float tot = fmaf(last, cmask, rest);
        // butterfly sum across lanes -> every lane holds the column total for step s
        tot += __shfl_xor_sync(0xffffffffu, tot, 16);
        tot += __shfl_xor_sync(0xffffffffu, tot, 8);
        tot += __shfl_xor_sync(0xffffffffu, tot, 4);
        tot += __shfl_xor_sync(0xffffffffu, tot, 2);
        tot += __shfl_xor_sync(0xffffffffu, tot, 1);
        if (lane == s) colreg += tot;     // lane l ends holding col j-row gj*32+l
    }

    // Diag correction: the self pair went through the same rounding path as the
    // loop body (f32x2 lane == scalar fma.rn) -> subtraction cancels exactly.
    float selfw = 0.0f;
    if (diag) {
        if (HS) selfw = eval1(xs, ys, zs, xs, ys, zs);
        else {
            float lx, hx, ly, hy, lz, hz;
            unpack2(xi[NPA - 1], lx, hx); unpack2(yi[NPA - 1], ly, hy);
            unpack2(zi[NPA - 1], lz, hz);
            selfw = eval1(hx, hy, hz, hx, hy, hz);
        }
    }

    #pragma unroll
    for (int p = 0; p < NP; ++p) {
        float lo, hi; unpack2(ra[p], lo, hi);
        raw[(gib + 2 * p) * 32 + lane] += lo;
        if (!HS && p == NP - 1) hi -= selfw;
        raw[(gib + 2 * p + 1) * 32 + lane] += hi;
    }
    if (HS) raw[(gib + 2 * NP) * 32 + lane] += ras - selfw;
    raw[gj * 32 + lane] += colreg;
}

__global__ __launch_bounds__(TPB, 8)
void normals_bcast_kernel(const float* __restrict__ normals,
                          float* __restrict__ out)
{
    __shared__ ull   sdx[NPTS], sdy[NPTS], sdz[NPTS];   // 12 KB duplicated pairs
    __shared__ float rowaccW[4][NPTS];                  // 8 KB per-warp row acc
    __shared__ float sred[3][4];

    const int b    = blockIdx.x >> 1;
    const int half = blockIdx.x & 1;
    const int t    = threadIdx.x;
    const int lane = t & 31;
    const int wl   = t >> 5;

    const float* base = normals + (size_t)b * NPTS * 3;
    #pragma unroll
    for (int r = t; r < NPTS; r += TPB) {
        float x = base[r * 3 + 0], y = base[r * 3 + 1], z = base[r * 3 + 2];
        sdx[r] = pack2(x, x); sdy[r] = pack2(y, y); sdz[r] = pack2(z, z);
    }
    #pragma unroll
    for (int idx = t; idx < 4 * NPTS; idx += TPB)
        ((float*)rowaccW)[idx] = 0.0f;
    __syncthreads();

    const int W = half * 4 + wl;          // global warp id 0..7
    float* raw = rowaccW[wl];

    #pragma unroll 1
    for (int c = 0; c < 5; ++c) {
        const int gj  = c_gj[W][c];
        const int gib = c_gib[W][c];
        const int ng  = c_ng[W][c];
        const bool dg = (gib + ng - 1 == gj);
        switch (ng) {
            case 4: if (dg) process_chunk<2, false>(sdx, sdy, sdz, raw, gj, gib, true,  lane);
                    else    process_chunk<2, false>(sdx, sdy, sdz, raw, gj, gib, false, lane);
                    break;
            case 3: process_chunk<1, true >(sdx, sdy, sdz, raw, gj, gib, dg, lane); break;
            case 2: process_chunk<1, false>(sdx, sdy, sdz, raw, gj, gib, dg, lane); break;
            default: process_chunk<0, true >(sdx, sdy, sdz, raw, gj, gib, dg, lane); break;
        }
    }
    __syncthreads();

    // weighted sum over rows handled by this thread
    float vx = 0.0f, vy = 0.0f, vz = 0.0f;
    #pragma unroll
    for (int r = t; r < NPTS; r += TPB) {
        float wsum = (rowaccW[0][r] + rowaccW[1][r])
                   + (rowaccW[2][r] + rowaccW[3][r]);
        float nx, ny, nz, t_;
        unpack2(sdx[r], nx, t_); unpack2(sdy[r], ny, t_); unpack2(sdz[r], nz, t_);
        vx = fmaf(wsum, nx, vx);
        vy = fmaf(wsum, ny, vy);
        vz = fmaf(wsum, nz, vz);
    }

    #pragma unroll
    for (int s = 16; s >= 1; s >>= 1) {
        vx += __shfl_down_sync(0xffffffffu, vx, s);
        vy += __shfl_down_sync(0xffffffffu, vy, s);
        vz += __shfl_down_sync(0xffffffffu, vz, s);
    }
    if (lane == 0) { sred[0][wl] = vx; sred[1][wl] = vy; sred[2][wl] = vz; }
    __syncthreads();

    if (t == 0) {
        float rx = (sred[0][0] + sred[0][1]) + (sred[0][2] + sred[0][3]);
        float ry = (sred[1][0] + sred[1][1]) + (sred[1][2] + sred[1][3]);
        float rz = (sred[2][0] + sred[2][1]) + (sred[2][2] + sred[2][3]);
        g_stage[blockIdx.x][0] = rx;
        g_stage[blockIdx.x][1] = ry;
        g_stage[blockIdx.x][2] = rz;
        __threadfence();
        int old = atomicAdd(&g_cnt[b], 1);
        if (old == 1) {
            __threadfence();
            const int other = blockIdx.x ^ 1;
            rx += g_stage[other][0];
            ry += g_stage[other][1];
            rz += g_stage[other][2];
            float ss  = fmaf(rx, rx, fmaf(ry, ry, rz * rz));
            float inv = rsqrtf(fmaxf(ss, 1e-20f));
            out[b * 3 + 0] = rx * inv;
            out[b * 3 + 1] = ry * inv;
            out[b * 3 + 2] = rz * inv;
            g_cnt[b] = 0;   // deterministic state for graph replay
        }
    }
}

extern "C" void kernel_launch(void* const* d_in, const int* in_sizes, int n_in,
                              void* d_out, int out_size)
{
    const float* normals = (const float*)d_in[0];  // [512, 512, 3] f32
    // d_in[1] = weights: unused by the reference math.
    float* out = (float*)d_out;                    // [512, 3] f32

    normals_bcast_kernel<<<1024, TPB>>>(normals, out);
}

// round 14
// speedup vs baseline: 1.2804x; 1.0819x over previous
#include <cuda_runtime.h>
#include <cuda_bf16.h>

// NormalsRenderer: B=512, N=512.
// out[b] = normalize( sum_i acc_i * n_i ),  acc_i = sum_{j!=i} exp(-acos(clip(<n_i,n_j>)))
// Identities (uniform positive scales cancel under the final normalize):
//   - division by max(new_weights) dropped; exp(-acos d) = const * exp(asin d)
//   - u = sat(1-|d|);  asin(|d|)*log2e = LHPI + sqrt(u)*Q(u)  (cubic Q)
//   - w = exp2( copysign( LHPI + sqrt(u)*Q(u), d ) )
// 512 rows = 16 groups of 32; 136 unordered group-tiles covered once by 40 chunks
// (<=4 i-groups x 1 j-group), 5 chunks/warp, 8 warps/batch (R9's proven table).
// BROADCAST-J loop: normals in smem as pre-duplicated packed pairs sdx[k]=(x_k,x_k);
// step s reads j-row gj*32+s with 3 broadcast LDS.64 (crossbar-free, pre-packed).
// COLUMN sums with NO shuffle chain: each step the lane stores its column
// contribution to a 9-padded per-warp scratch slot (1 STS.32, no dependences);
// every 8 steps a conflict-free transposed read (x9 padding => distinct banks)
// + 2 independent shfls reduces 8 columns and RMWs them into the row array.
// Diag chunk: diag group LAST; excluded from columns via fmaf(last,cmask,rest);
// s=0..31 self term stays in rowacc, one bitwise-identical eval subtracted at flush.
// 2 CTAs/batch (grid 1024, 128 thr); per-warp smem row accumulators, CTA reduce,
// cross-CTA merge via atomic counter (second finisher normalizes + writes).

#define NPTS 512
#define TPB  128

typedef unsigned long long ull;
typedef unsigned int uint;

// -log2(e) * p_AS(1-u) re-expanded in u, and log2(e)*pi/2
#define Q0f (-2.0401824f)
#define Q1f (-0.17280645f)
#define Q2f (-0.026074023f)
#define Q3f (-0.027020667f)
#define LHPIf (2.2661800709f)

__device__ float g_stage[1024][3];
__device__ int   g_cnt[512];

// R9's proven chunk tables: warp W (0..7) runs 5 chunks (gj, gib, ng).
// Exact cover of all 136 (i<=j) group-tiles; diag iff gib+ng-1 == gj (always last).
__constant__ signed char c_gj[8][5] = {
    {3,4,5,6,0}, {7,7,8,8,4}, {9,9,10,10,8}, {11,11,11,12,12},
    {12,12,13,2,1}, {13,13,14,6,5}, {14,14,15,10,9}, {15,15,15,14,13}};
__constant__ signed char c_gib[8][5] = {
    {0,0,0,0,0}, {0,4,0,4,4}, {0,4,0,4,8}, {0,4,8,0,12},
    {4,8,0,0,0}, {4,8,0,4,4}, {4,8,0,8,8}, {4,8,12,12,12}};
__constant__ signed char c_ng[8][5] = {
    {4,4,4,4,1}, {4,4,4,4,1}, {4,4,4,4,1}, {4,4,4,4,1},
    {4,4,4,3,2}, {4,4,4,3,2}, {4,4,4,3,2}, {4,4,4,3,2}};

__device__ __forceinline__ ull pack2(float lo, float hi) {
    ull r; asm("mov.b64 %0, {%1, %2};" : "=l"(r) : "f"(lo), "f"(hi)); return r;
}
__device__ __forceinline__ void unpack2(ull v, float& lo, float& hi) {
    asm("mov.b64 {%0, %1}, %2;" : "=f"(lo), "=f"(hi) : "l"(v));
}
__device__ __forceinline__ ull fma2(ull a, ull b, ull c) {
    ull d; asm("fma.rn.f32x2 %0, %1, %2, %3;" : "=l"(d) : "l"(a), "l"(b), "l"(c)); return d;
}
__device__ __forceinline__ ull mul2(ull a, ull b) {
    ull d; asm("mul.rn.f32x2 %0, %1, %2;" : "=l"(d) : "l"(a), "l"(b)); return d;
}
__device__ __forceinline__ ull add2(ull a, ull b) {
    ull d; asm("add.rn.f32x2 %0, %1, %2;" : "=l"(d) : "l"(a), "l"(b)); return d;
}
__device__ __forceinline__ float sqrta(float x) {
    float r; asm("sqrt.approx.f32 %0, %1;" : "=f"(r) : "f"(x)); return r;
}
__device__ __forceinline__ float ex2a(float x) {
    float r; asm("ex2.approx.f32 %0, %1;" : "=f"(r) : "f"(x)); return r;
}

__device__ __forceinline__ ull eval2(ull xi2, ull yi2, ull zi2,
                                     ull jx2, ull jy2, ull jz2)
{
    const ull q3v = pack2(Q3f, Q3f), q2v = pack2(Q2f, Q2f);
    const ull q1v = pack2(Q1f, Q1f), q0v = pack2(Q0f, Q0f);
    const ull lh2 = pack2(LHPIf, LHPIf);
    ull d2 = fma2(zi2, jz2, fma2(yi2, jy2, mul2(xi2, jx2)));
    float da, db; unpack2(d2, da, db);
    float ua = __saturatef(1.0f - fabsf(da));
    float ub = __saturatef(1.0f - fabsf(db));
    float sa = sqrta(ua), sb = sqrta(ub);
    ull u2 = pack2(ua, ub);
    ull p2 = fma2(u2, q3v, q2v);
    p2 = fma2(u2, p2, q1v);
    p2 = fma2(u2, p2, q0v);
    ull g2 = fma2(pack2(sa, sb), p2, lh2);
    float ga, gb; unpack2(g2, ga, gb);
    uint ea = __float_as_uint(ga) | (__float_as_uint(da) & 0x80000000u);
    uint eb = __float_as_uint(gb) | (__float_as_uint(db) & 0x80000000u);
    return pack2(ex2a(__uint_as_float(ea)), ex2a(__uint_as_float(eb)));
}

__device__ __forceinline__ float eval1(float xi, float yi, float zi,
                                       float jx, float jy, float jz)
{
    float d = fmaf(zi, jz, fmaf(yi, jy, xi * jx));
    float u = __saturatef(1.0f - fabsf(d));
    float s = sqrta(u);
    float p = fmaf(u, Q3f, Q2f);
    p = fmaf(u, p, Q1f);
    p = fmaf(u, p, Q0f);
    float g = fmaf(s, p, LHPIf);
    uint  e = __float_as_uint(g) | (__float_as_uint(d) & 0x80000000u);
    return ex2a(__uint_as_float(e));
}

// NP packed group-pairs + optional scalar tail. NG = 2*NP + HS. Diag group = last.
template<int NP, bool HS>
__device__ __forceinline__ void process_chunk(const ull* __restrict__ sdx,
                                              const ull* __restrict__ sdy,
                                              const ull* __restrict__ sdz,
                                              float* __restrict__ raw,
                                              float* __restrict__ scratch,  // 288 floats, this warp
                                              int gj, int gib, bool diag, int lane)
{
    const float* fsx = (const float*)sdx;   // fsx[2*r] = x_r (lo half)
    const float* fsy = (const float*)sdy;
    const float* fsz = (const float*)sdz;

    constexpr int NPA = (NP > 0) ? NP : 1;
    ull xi[NPA], yi[NPA], zi[NPA], ra[NPA];
    #pragma unroll
    for (int p = 0; p < NP; ++p) {
        const int rA = (gib + 2 * p) * 32 + lane;
        const int rB = rA + 32;
        xi[p] = pack2(fsx[2 * rA], fsx[2 * rB]);
        yi[p] = pack2(fsy[2 * rA], fsy[2 * rB]);
        zi[p] = pack2(fsz[2 * rA], fsz[2 * rB]);
        ra[p] = pack2(0.0f, 0.0f);
    }
    float xs = 0.0f, ys = 0.0f, zs = 0.0f, ras = 0.0f;
    if (HS) {
        const int r = (gib + 2 * NP) * 32 + lane;
        xs = fsx[2 * r]; ys = fsy[2 * r]; zs = fsz[2 * r];
    }

    const int jbase = gj * 32;
    const float cmask = diag ? 0.0f : 1.0f;   // last group excluded from columns if diag
    const int q  = lane >> 2;                 // flush: this lane reduces column q
    const int rb = (lane & 3) * 8;            // over scratch rows rb..rb+7

    #pragma unroll 1
    for (int bq = 0; bq < 4; ++bq) {
        #pragma unroll
        for (int sq = 0; sq < 8; ++sq) {
            const int s = bq * 8 + sq;
            const ull jx2 = sdx[jbase + s];   // broadcast LDS.64, pre-packed (j,j)
            const ull jy2 = sdy[jbase + s];
            const ull jz2 = sdz[jbase + s];
            float rest = 0.0f, last;
            if (NP >= 1) {
                ull w0 = eval2(xi[0], yi[0], zi[0], jx2, jy2, jz2);
                ra[0] = add2(ra[0], w0);
                float a0, b0; unpack2(w0, a0, b0);
                if (NP == 1 && !HS) { rest = a0; last = b0; }
                else                  rest = a0 + b0;
            }
            if (NP == 2) {
                ull w1 = eval2(xi[1], yi[1], zi[1], jx2, jy2, jz2);
                ra[1] = add2(ra[1], w1);
                float a1, b1; unpack2(w1, a1, b1);
                if (!HS) { rest += a1; last = b1; }
                else       rest += a1 + b1;
            }
            if (HS) {
                float jxs, jys, jzs, t_;
                unpack2(jx2, jxs, t_); unpack2(jy2, jys, t_); unpack2(jz2, jzs, t_);
                float ws = eval1(xs, ys, zs, jxs, jys, jzs);
                ras += ws;
                last = ws;
            }
            scratch[lane * 9 + sq] = fmaf(last, cmask, rest);   // fire-and-forget STS
        }
        __syncwarp();
        // transposed conflict-free reduce of 8 columns (x9 pad => distinct banks)
        float sum = ((scratch[(rb + 0) * 9 + q] + scratch[(rb + 1) * 9 + q])
                   + (scratch[(rb + 2) * 9 + q] + scratch[(rb + 3) * 9 + q]))
                  + ((scratch[(rb + 4) * 9 + q] + scratch[(rb + 5) * 9 + q])
                   + (scratch[(rb + 6) * 9 + q] + scratch[(rb + 7) * 9 + q]));
        sum += __shfl_xor_sync(0xffffffffu, sum, 1);
        sum += __shfl_xor_sync(0xffffffffu, sum, 2);
        if ((lane & 3) == 0) raw[jbase + bq * 8 + q] += sum;
        __syncwarp();
    }

    // Diag correction: self pair went through the same rounding path (f32x2 lane
    // == scalar fma.rn) -> subtraction cancels exactly.
    float selfw = 0.0f;
    if (diag) {
        if (HS) selfw = eval1(xs, ys, zs, xs, ys, zs);
        else {
            float lx, hx, ly, hy, lz, hz;
            unpack2(xi[NPA - 1], lx, hx); unpack2(yi[NPA - 1], ly, hy);
            unpack2(zi[NPA - 1], lz, hz);
            selfw = eval1(hx, hy, hz, hx, hy, hz);
        }
    }

    #pragma unroll
    for (int p = 0; p < NP; ++p) {
        float lo, hi; unpack2(ra[p], lo, hi);
        raw[(gib + 2 * p) * 32 + lane] += lo;
        if (!HS && p == NP - 1) hi -= selfw;
        raw[(gib + 2 * p + 1) * 32 + lane] += hi;
    }
    if (HS) raw[(gib + 2 * NP) * 32 + lane] += ras - selfw;
}

__global__ __launch_bounds__(TPB, 8)
void normals_bcast2_kernel(const float* __restrict__ normals,
                           float* __restrict__ out)
{
    __shared__ ull   sdx[NPTS], sdy[NPTS], sdz[NPTS];   // 12 KB duplicated pairs
    __shared__ float rowaccW[4][NPTS];                  // 8 KB per-warp row acc
    __shared__ float colscratch[4][288];                // 4.5 KB per-warp (9-padded)
    __shared__ float sred[3][4];

    const int b    = blockIdx.x >> 1;
    const int half = blockIdx.x & 1;
    const int t    = threadIdx.x;
    const int lane = t & 31;
    const int wl   = t >> 5;

    const float* base = normals + (size_t)b * NPTS * 3;
    #pragma unroll
    for (int r = t; r < NPTS; r += TPB) {
        float x = base[r * 3 + 0], y = base[r * 3 + 1], z = base[r * 3 + 2];
        sdx[r] = pack2(x, x); sdy[r] = pack2(y, y); sdz[r] = pack2(z, z);
    }
    #pragma unroll
    for (int idx = t; idx < 4 * NPTS; idx += TPB)
        ((float*)rowaccW)[idx] = 0.0f;
    __syncthreads();

    const int W = half * 4 + wl;          // global warp id 0..7
    float* raw = rowaccW[wl];
    float* scr = colscratch[wl];

    #pragma unroll 1
    for (int c = 0; c < 5; ++c) {
        const int gj  = c_gj[W][c];
        const int gib = c_gib[W][c];
        const int ng  = c_ng[W][c];
        const bool dg = (gib + ng - 1 == gj);
        switch (ng) {
            case 4: process_chunk<2, false>(sdx, sdy, sdz, raw, scr, gj, gib, dg, lane); break;
            case 3: process_chunk<1, true >(sdx, sdy, sdz, raw, scr, gj, gib, dg, lane); break;
            case 2: process_chunk<1, false>(sdx, sdy, sdz, raw, scr, gj, gib, dg, lane); break;
            default: process_chunk<0, true >(sdx, sdy, sdz, raw, scr, gj, gib, dg, lane); break;
        }
    }
    __syncthreads();

    // weighted sum over rows handled by this thread
    float vx = 0.0f, vy = 0.0f, vz = 0.0f;
    #pragma unroll
    for (int r = t; r < NPTS; r += TPB) {
        float wsum = (rowaccW[0][r] + rowaccW[1][r])
                   + (rowaccW[2][r] + rowaccW[3][r]);
        float nx = ((const float*)sdx)[2 * r];
        float ny = ((const float*)sdy)[2 * r];
        float nz = ((const float*)sdz)[2 * r];
        vx = fmaf(wsum, nx, vx);
        vy = fmaf(wsum, ny, vy);
        vz = fmaf(wsum, nz, vz);
    }

    #pragma unroll
    for (int s = 16; s >= 1; s >>= 1) {
        vx += __shfl_down_sync(0xffffffffu, vx, s);
        vy += __shfl_down_sync(0xffffffffu, vy, s);
        vz += __shfl_down_sync(0xffffffffu, vz, s);
    }
    if (lane == 0) { sred[0][wl] = vx; sred[1][wl] = vy; sred[2][wl] = vz; }
    __syncthreads();

    if (t == 0) {
        float rx = (sred[0][0] + sred[0][1]) + (sred[0][2] + sred[0][3]);
        float ry = (sred[1][0] + sred[1][1]) + (sred[1][2] + sred[1][3]);
        float rz = (sred[2][0] + sred[2][1]) + (sred[2][2] + sred[2][3]);
        g_stage[blockIdx.x][0] = rx;
        g_stage[blockIdx.x][1] = ry;
        g_stage[blockIdx.x][2] = rz;
        __threadfence();
        int old = atomicAdd(&g_cnt[b], 1);
        if (old == 1) {
            __threadfence();
            const int other = blockIdx.x ^ 1;
            rx += g_stage[other][0];
            ry += g_stage[other][1];
            rz += g_stage[other][2];
            float ss  = fmaf(rx, rx, fmaf(ry, ry, rz * rz));
            float inv = rsqrtf(fmaxf(ss, 1e-20f));
            out[b * 3 + 0] = rx * inv;
            out[b * 3 + 1] = ry * inv;
            out[b * 3 + 2] = rz * inv;
            g_cnt[b] = 0;   // deterministic state for graph replay
        }
    }
}

extern "C" void kernel_launch(void* const* d_in, const int* in_sizes, int n_in,
                              void* d_out, int out_size)
{
    const float* normals = (const float*)d_in[0];  // [512, 512, 3] f32
    // d_in[1] = weights: unused by the reference math.
    float* out = (float*)d_out;                    // [512, 3] f32

    normals_bcast2_kernel<<<1024, TPB>>>(normals, out);
}

// round 15
// speedup vs baseline: 1.2811x; 1.0006x over previous
#include <cuda_runtime.h>
#include <cuda_bf16.h>

// NormalsRenderer: B=512, N=512.
// out[b] = normalize( sum_i acc_i * n_i ),  acc_i = sum_{j!=i} exp(-acos(clip(<n_i,n_j>)))
// Identities (uniform positive scales cancel under the final normalize):
//   - division by max(new_weights) dropped; exp(-acos d) = const * exp(asin d)
//   - u = sat(1-|d|);  asin(|d|)*log2e = LHPI + sqrt(u)*Q(u)  (cubic Q)
//   - w = exp2( copysign( LHPI + sqrt(u)*Q(u), d ) )
// 512 rows = 16 groups of 32; 136 unordered group-tiles covered exactly once by 40
// chunks (<=4 i-groups x 1 j-group) spread over 16 warps/batch = 4 CTAs x 4 warps
// (grid 2048) — R12's proven table. Broadcast-j inner loop (R14's proven body):
// normals in smem as pre-duplicated packed pairs sdx[k]=(x_k,x_k); step s reads
// j-row gj*32+s via 3 broadcast LDS.64. Column sums via per-warp 9-padded scratch
// (1 STS.32/step) + conflict-free transposed reduce every 8 steps.
// Diag chunk (runtime): diag group LAST; excluded from columns via fmaf(last,cmask);
// self term stays in rowacc, one bitwise-identical eval subtracted at flush.
// __launch_bounds__(128,9) caps regs at 56 -> up to 9 CTAs/SM (36 warps) for
// latency hiding (R14 measured issue=69.6% at 28-warp occupancy = latency-bound).
// Per-warp smem row accumulators, CTA reduce, 4-way cross-CTA atomic merge.

#define NPTS 512
#define TPB  128

typedef unsigned long long ull;
typedef unsigned int uint;

// -log2(e) * p_AS(1-u) re-expanded in u, and log2(e)*pi/2
#define Q0f (-2.0401824f)
#define Q1f (-0.17280645f)
#define Q2f (-0.026074023f)
#define Q3f (-0.027020667f)
#define LHPIf (2.2661800709f)

__device__ float g_stage[2048][3];
__device__ int   g_cnt[512];

// R12's proven 16-warp chunk tables: warp W (0..15) runs up to 3 chunks
// (gj, gib, ng); ng=0 sentinel. Exact cover of all 136 (i<=j) group-tiles;
// diag iff gib+ng-1 == gj (diag group always last in its run).
__constant__ signed char c_gj[16][3] = {
    {3,15,-1},{4,15,-1},{5,15,-1},{6,14,-1},{7,14,-1},{8,13,-1},{9,13,-1},{10,12,-1},
    {11,12,4},{12,11,8},{13,11,12},{14,10,0},{15,2,1},{7,6,5},{8,10,9},{9,14,13}};
__constant__ signed char c_gib[16][3] = {
    {0,0,0},{1,4,0},{2,8,0},{3,3,0},{4,7,0},{5,2,0},{6,6,0},{7,1,0},
    {8,5,0},{9,0,0},{10,4,0},{11,3,0},{12,0,0},{0,0,0},{1,0,0},{2,0,0}};
__constant__ signed char c_ng[16][3] = {
    {4,4,0},{4,4,0},{4,4,0},{4,4,0},{4,4,0},{4,4,0},{4,4,0},{4,4,0},
    {4,4,1},{4,4,1},{4,4,1},{4,4,1},{4,3,2},{4,3,2},{4,3,2},{4,3,2}};

__device__ __forceinline__ ull pack2(float lo, float hi) {
    ull r; asm("mov.b64 %0, {%1, %2};" : "=l"(r) : "f"(lo), "f"(hi)); return r;
}
__device__ __forceinline__ void unpack2(ull v, float& lo, float& hi) {
    asm("mov.b64 {%0, %1}, %2;" : "=f"(lo), "=f"(hi) : "l"(v));
}
__device__ __forceinline__ ull fma2(ull a, ull b, ull c) {
    ull d; asm("fma.rn.f32x2 %0, %1, %2, %3;" : "=l"(d) : "l"(a), "l"(b), "l"(c)); return d;
}
__device__ __forceinline__ ull mul2(ull a, ull b) {
    ull d; asm("mul.rn.f32x2 %0, %1, %2;" : "=l"(d) : "l"(a), "l"(b)); return d;
}
__device__ __forceinline__ ull add2(ull a, ull b) {
    ull d; asm("add.rn.f32x2 %0, %1, %2;" : "=l"(d) : "l"(a), "l"(b)); return d;
}
__device__ __forceinline__ float sqrta(float x) {
    float r; asm("sqrt.approx.f32 %0, %1;" : "=f"(r) : "f"(x)); return r;
}
__device__ __forceinline__ float ex2a(float x) {
    float r; asm("ex2.approx.f32 %0, %1;" : "=f"(r) : "f"(x)); return r;
}

__device__ __forceinline__ ull eval2(ull xi2, ull yi2, ull zi2,
                                     ull jx2, ull jy2, ull jz2)
{
    const ull q3v = pack2(Q3f, Q3f), q2v = pack2(Q2f, Q2f);
    const ull q1v = pack2(Q1f, Q1f), q0v = pack2(Q0f, Q0f);
    const ull lh2 = pack2(LHPIf, LHPIf);
    ull d2 = fma2(zi2, jz2, fma2(yi2, jy2, mul2(xi2, jx2)));
    float da, db; unpack2(d2, da, db);
    float ua = __saturatef(1.0f - fabsf(da));
    float ub = __saturatef(1.0f - fabsf(db));
    float sa = sqrta(ua), sb = sqrta(ub);
    ull u2 = pack2(ua, ub);
    ull p2 = fma2(u2, q3v, q2v);
    p2 = fma2(u2, p2, q1v);
    p2 = fma2(u2, p2, q0v);
    ull g2 = fma2(pack2(sa, sb), p2, lh2);
    float ga, gb; unpack2(g2, ga, gb);
    uint ea = __float_as_uint(ga) | (__float_as_uint(da) & 0x80000000u);
    uint eb = __float_as_uint(gb) | (__float_as_uint(db) & 0x80000000u);
    return pack2(ex2a(__uint_as_float(ea)), ex2a(__uint_as_float(eb)));
}

__device__ __forceinline__ float eval1(float xi, float yi, float zi,
                                       float jx, float jy, float jz)
{
    float d = fmaf(zi, jz, fmaf(yi, jy, xi * jx));
    float u = __saturatef(1.0f - fabsf(d));
    float s = sqrta(u);
    float p = fmaf(u, Q3f, Q2f);
    p = fmaf(u, p, Q1f);
    p = fmaf(u, p, Q0f);
    float g = fmaf(s, p, LHPIf);
    uint  e = __float_as_uint(g) | (__float_as_uint(d) & 0x80000000u);
    return ex2a(__uint_as_float(e));
}

// NP packed group-pairs + optional scalar tail. NG = 2*NP + HS. Diag group = last.
template<int NP, bool HS>
__device__ __forceinline__ void process_chunk(const ull* __restrict__ sdx,
                                              const ull* __restrict__ sdy,
                                              const ull* __restrict__ sdz,
                                              float* __restrict__ raw,
                                              float* __restrict__ scratch,  // 288 floats, this warp
                                              int gj, int gib, bool diag, int lane)
{
    const float* fsx = (const float*)sdx;   // fsx[2*r] = x_r (lo half)
    const float* fsy = (const float*)sdy;
    const float* fsz = (const float*)sdz;

    constexpr int NPA = (NP > 0) ? NP : 1;
    ull xi[NPA], yi[NPA], zi[NPA], ra[NPA];
    #pragma unroll
    for (int p = 0; p < NP; ++p) {
        const int rA = (gib + 2 * p) * 32 + lane;
        const int rB = rA + 32;
        xi[p] = pack2(fsx[2 * rA], fsx[2 * rB]);
        yi[p] = pack2(fsy[2 * rA], fsy[2 * rB]);
        zi[p] = pack2(fsz[2 * rA], fsz[2 * rB]);
        ra[p] = pack2(0.0f, 0.0f);
    }
    float xs = 0.0f, ys = 0.0f, zs = 0.0f, ras = 0.0f;
    if (HS) {
        const int r = (gib + 2 * NP) * 32 + lane;
        xs = fsx[2 * r]; ys = fsy[2 * r]; zs = fsz[2 * r];
    }

    const int jbase = gj * 32;
    const float cmask = diag ? 0.0f : 1.0f;   // last group excluded from columns if diag
    const int q  = lane >> 2;                 // flush: this lane reduces column q
    const int rb = (lane & 3) * 8;            // over scratch rows rb..rb+7

    #pragma unroll 1
    for (int bq = 0; bq < 4; ++bq) {
        #pragma unroll
        for (int sq = 0; sq < 8; ++sq) {
            const int s = bq * 8 + sq;
            const ull jx2 = sdx[jbase + s];   // broadcast LDS.64, pre-packed (j,j)
            const ull jy2 = sdy[jbase + s];
            const ull jz2 = sdz[jbase + s];
            float rest = 0.0f, last;
            if (NP >= 1) {
                ull w0 = eval2(xi[0], yi[0], zi[0], jx2, jy2, jz2);
                ra[0] = add2(ra[0], w0);
                float a0, b0; unpack2(w0, a0, b0);
                if (NP == 1 && !HS) { rest = a0; last = b0; }
                else                  rest = a0 + b0;
            }
            if (NP == 2) {
                ull w1 = eval2(xi[1], yi[1], zi[1], jx2, jy2, jz2);
                ra[1] = add2(ra[1], w1);
                float a1, b1; unpack2(w1, a1, b1);
                if (!HS) { rest += a1; last = b1; }
                else       rest += a1 + b1;
            }
            if (HS) {
                float jxs, jys, jzs, t_;
                unpack2(jx2, jxs, t_); unpack2(jy2, jys, t_); unpack2(jz2, jzs, t_);
                float ws = eval1(xs, ys, zs, jxs, jys, jzs);
                ras += ws;
                last = ws;
            }
            scratch[lane * 9 + sq] = fmaf(last, cmask, rest);   // fire-and-forget STS
        }
        __syncwarp();
        // transposed conflict-free reduce of 8 columns (x9 pad => distinct banks)
        float sum = ((scratch[(rb + 0) * 9 + q] + scratch[(rb + 1) * 9 + q])
                   + (scratch[(rb + 2) * 9 + q] + scratch[(rb + 3) * 9 + q]))
                  + ((scratch[(rb + 4) * 9 + q] + scratch[(rb + 5) * 9 + q])
                   + (scratch[(rb + 6) * 9 + q] + scratch[(rb + 7) * 9 + q]));
        sum += __shfl_xor_sync(0xffffffffu, sum, 1);
        sum += __shfl_xor_sync(0xffffffffu, sum, 2);
        if ((lane & 3) == 0) raw[jbase + bq * 8 + q] += sum;
        __syncwarp();
    }

    // Diag correction: self pair went through the same rounding path (f32x2 lane
    // == scalar fma.rn) -> subtraction cancels exactly.
    float selfw = 0.0f;
    if (diag) {
        if (HS) selfw = eval1(xs, ys, zs, xs, ys, zs);
        else {
            float lx, hx, ly, hy, lz, hz;
            unpack2(xi[NPA - 1], lx, hx); unpack2(yi[NPA - 1], ly, hy);
            unpack2(zi[NPA - 1], lz, hz);
            selfw = eval1(hx, hy, hz, hx, hy, hz);
        }
    }

    #pragma unroll
    for (int p = 0; p < NP; ++p) {
        float lo, hi; unpack2(ra[p], lo, hi);
        raw[(gib + 2 * p) * 32 + lane] += lo;
        if (!HS && p == NP - 1) hi -= selfw;
        raw[(gib + 2 * p + 1) * 32 + lane] += hi;
    }
    if (HS) raw[(gib + 2 * NP) * 32 + lane] += ras - selfw;
}

__global__ __launch_bounds__(TPB, 9)
void normals_occ_kernel(const float* __restrict__ normals,
                        float* __restrict__ out)
{
    __shared__ ull   sdx[NPTS], sdy[NPTS], sdz[NPTS];   // 12 KB duplicated pairs
    __shared__ float rowaccW[4][NPTS];                  // 8 KB per-warp row acc
    __shared__ float colscratch[4][288];                // 4.5 KB per-warp (9-padded)
    __shared__ float sred[3][4];

    const int b  = blockIdx.x >> 2;       // batch
    const int qr = blockIdx.x & 3;        // quarter within batch
    const int t    = threadIdx.x;
    const int lane = t & 31;
    const int wl   = t >> 5;

    const float* base = normals + (size_t)b * NPTS * 3;
    #pragma unroll
    for (int r = t; r < NPTS; r += TPB) {
        float x = base[r * 3 + 0], y = base[r * 3 + 1], z = base[r * 3 + 2];
        sdx[r] = pack2(x, x); sdy[r] = pack2(y, y); sdz[r] = pack2(z, z);
    }
    #pragma unroll
    for (int idx = t; idx < 4 * NPTS; idx += TPB)
        ((float*)rowaccW)[idx] = 0.0f;
    __syncthreads();

    const int W = qr * 4 + wl;            // global warp id 0..15
    float* raw = rowaccW[wl];
    float* scr = colscratch[wl];

    #pragma unroll 1
    for (int c = 0; c < 3; ++c) {
        const int ng = c_ng[W][c];
        if (ng == 0) break;
        const int gj  = c_gj[W][c];
        const int gib = c_gib[W][c];
        const bool dg = (gib + ng - 1 == gj);
        switch (ng) {
            case 4: process_chunk<2, false>(sdx, sdy, sdz, raw, scr, gj, gib, dg, lane); break;
            case 3: process_chunk<1, true >(sdx, sdy, sdz, raw, scr, gj, gib, dg, lane); break;
            case 2: process_chunk<1, false>(sdx, sdy, sdz, raw, scr, gj, gib, dg, lane); break;
            default: process_chunk<0, true >(sdx, sdy, sdz, raw, scr, gj, gib, dg, lane); break;
        }
    }
    __syncthreads();

    // weighted sum over rows handled by this thread
    float vx = 0.0f, vy = 0.0f, vz = 0.0f;
    #pragma unroll
    for (int r = t; r < NPTS; r += TPB) {
        float wsum = (rowaccW[0][r] + rowaccW[1][r])
                   + (rowaccW[2][r] + rowaccW[3][r]);
        float nx = ((const float*)sdx)[2 * r];
        float ny = ((const float*)sdy)[2 * r];
        float nz = ((const float*)sdz)[2 * r];
        vx = fmaf(wsum, nx, vx);
        vy = fmaf(wsum, ny, vy);
        vz = fmaf(wsum, nz, vz);
    }

    #pragma unroll
    for (int s = 16; s >= 1; s >>= 1) {
        vx += __shfl_down_sync(0xffffffffu, vx, s);
        vy += __shfl_down_sync(0xffffffffu, vy, s);
        vz += __shfl_down_sync(0xffffffffu, vz, s);
    }
    if (lane == 0) { sred[0][wl] = vx; sred[1][wl] = vy; sred[2][wl] = vz; }
    __syncthreads();

    if (t == 0) {
        float rx = (sred[0][0] + sred[0][1]) + (sred[0][2] + sred[0][3]);
        float ry = (sred[1][0] + sred[1][1]) + (sred[1][2] + sred[1][3]);
        float rz = (sred[2][0] + sred[2][1]) + (sred[2][2] + sred[2][3]);
        g_stage[blockIdx.x][0] = rx;
        g_stage[blockIdx.x][1] = ry;
        g_stage[blockIdx.x][2] = rz;
        __threadfence();
        int old = atomicAdd(&g_cnt[b], 1);
        if (old == 3) {   // 4th arrival: combine all quarters + normalize + write
            __threadfence();
            const int baseIdx = b * 4;
            rx = 0.0f; ry = 0.0f; rz = 0.0f;
            #pragma unroll
            for (int k = 0; k < 4; ++k) {
                rx += g_stage[baseIdx + k][0];
                ry += g_stage[baseIdx + k][1];
                rz += g_stage[baseIdx + k][2];
            }
            float ss  = fmaf(rx, rx, fmaf(ry, ry, rz * rz));
            float inv = rsqrtf(fmaxf(ss, 1e-20f));
            out[b * 3 + 0] = rx * inv;
            out[b * 3 + 1] = ry * inv;
            out[b * 3 + 2] = rz * inv;
            g_cnt[b] = 0;   // deterministic state for graph replay
        }
    }
}

extern "C" void kernel_launch(void* const* d_in, const int* in_sizes, int n_in,
                              void* d_out, int out_size)
{
    const float* normals = (const float*)d_in[0];  // [512, 512, 3] f32
    // d_in[1] = weights: unused by the reference math.
    float* out = (float*)d_out;                    // [512, 3] f32

    normals_occ_kernel<<<2048, TPB>>>(normals, out);
}